// round 6
// baseline (speedup 1.0000x reference)
#include <cuda_runtime.h>

// Problem constants (fixed by the reference: mulElements hard-codes 8000 rows)
#define NN 8000
#define DD 9
#define NJ4 (NN / 4)            // 2000 float4 per output row
#define ROWS_PER_BLOCK 32

// Scratch (allocation-free rule: __device__ globals)
__device__ float g_z1[NN];      // per-row sum ((x-c1)/a1)^2
__device__ float g_z2[NN];
__device__ float g_f1[NN];      // x @ w_fc1.T + b_fc1
__device__ float g_f2[NN];
__device__ float g_w1b[NN];     // normalized cumulative weights
__device__ float g_w2b[NN];

// ---------------------------------------------------------------------------
// Fused prologue: ONE block of 1024 threads.
//   Phase A: per-row quadratic sums + the two 9->1 dot products (8 rows/thread,
//            x lines are L1-resident so the strided 36B rows are cheap).
//   Phase B: 8000-element inclusive prefix sum of (z1,z2), then
//            w = exp(-prefix), normalized.  cumprod(prod(exp(-z)))
//            == exp(-cumsum(sum(z))), so no sequential product needed.
// threadfence_block + __syncthreads orders the global g_z writes before
// Phase B reads them (single block, so block scope suffices).
// ---------------------------------------------------------------------------
__global__ __launch_bounds__(1024) void prologue_kernel(
        const float* __restrict__ x,
        const float* __restrict__ a1,
        const float* __restrict__ c1,
        const float* __restrict__ a2,
        const float* __restrict__ c2,
        const float* __restrict__ wfc1,
        const float* __restrict__ bfc1,
        const float* __restrict__ wfc2,
        const float* __restrict__ bfc2) {
    const int tid = threadIdx.x;
    const int lane = tid & 31;
    const int wid = tid >> 5;

    // ---- Phase A: row stats ----
    {
        const float ia1 = 1.0f / a1[0];
        const float ia2 = 1.0f / a2[0];
        const float cc1 = c1[0];
        const float cc2 = c2[0];
        const float b1 = bfc1[0];
        const float b2 = bfc2[0];
        float wf1[DD], wf2[DD];
#pragma unroll
        for (int j = 0; j < DD; j++) { wf1[j] = wfc1[j]; wf2[j] = wfc2[j]; }

        for (int i = tid; i < NN; i += 1024) {
            float z1 = 0.0f, z2 = 0.0f;
            float f1 = b1, f2 = b2;
#pragma unroll
            for (int j = 0; j < DD; j++) {
                float v = x[i * DD + j];
                float t1 = (v - cc1) * ia1;
                float t2 = (v - cc2) * ia2;
                z1 = fmaf(t1, t1, z1);
                z2 = fmaf(t2, t2, z2);
                f1 = fmaf(v, wf1[j], f1);
                f2 = fmaf(v, wf2[j], f2);
            }
            g_z1[i] = z1;
            g_z2[i] = z2;
            g_f1[i] = f1;
            g_f2[i] = f2;
        }
    }
    __threadfence_block();
    __syncthreads();   // g_z writes visible block-wide

    // ---- Phase B: block scan over 8 chunks of 1024 ----
    __shared__ float2 s_warp[32];
    __shared__ float2 s_carry;
    if (tid == 0) s_carry = make_float2(0.0f, 0.0f);
    __syncthreads();

    for (int base = 0; base < NN; base += 1024) {
        int i = base + tid;
        float a = (i < NN) ? g_z1[i] : 0.0f;
        float b = (i < NN) ? g_z2[i] : 0.0f;

        // warp-level inclusive scan (float2)
#pragma unroll
        for (int off = 1; off < 32; off <<= 1) {
            float ta = __shfl_up_sync(0xffffffffu, a, off);
            float tb = __shfl_up_sync(0xffffffffu, b, off);
            if (lane >= off) { a += ta; b += tb; }
        }
        if (lane == 31) s_warp[wid] = make_float2(a, b);
        __syncthreads();

        if (wid == 0) {
            float wa = s_warp[lane].x;
            float wb = s_warp[lane].y;
#pragma unroll
            for (int off = 1; off < 32; off <<= 1) {
                float ta = __shfl_up_sync(0xffffffffu, wa, off);
                float tb = __shfl_up_sync(0xffffffffu, wb, off);
                if (lane >= off) { wa += ta; wb += tb; }
            }
            s_warp[lane] = make_float2(wa, wb);
        }
        __syncthreads();

        float offa = s_carry.x, offb = s_carry.y;
        if (wid > 0) { offa += s_warp[wid - 1].x; offb += s_warp[wid - 1].y; }
        float s1 = a + offa;
        float s2 = b + offb;

        if (i < NN) {
            float w1 = expf(-s1);
            float w2 = expf(-s2);
            float inv = 1.0f / (w1 + w2);
            g_w1b[i] = w1 * inv;
            g_w2b[i] = w2 * inv;
        }

        __syncthreads();   // all reads of s_warp/s_carry done
        if (tid == 0) {
            s_carry = make_float2(s_carry.x + s_warp[31].x,
                                  s_carry.y + s_warp[31].y);
        }
        __syncthreads();
    }
}

// ---------------------------------------------------------------------------
// Outer product: out[i][j] = f1[i]*w1b[j] + f2[i]*w2b[j]. 256 MB of stores —
// the LTS/DRAM-write roofline. float4 stores; 32 rows per block reuse the w
// float4s in registers (w L2 read traffic: 16 MB total vs 64 MB at 8 rows).
// ---------------------------------------------------------------------------
__global__ __launch_bounds__(256) void outer_kernel(float4* __restrict__ out) {
    int j4 = blockIdx.x * blockDim.x + threadIdx.x;
    if (j4 >= NJ4) return;

    const float4 w1 = reinterpret_cast<const float4*>(g_w1b)[j4];
    const float4 w2 = reinterpret_cast<const float4*>(g_w2b)[j4];

    const int i0 = blockIdx.y * ROWS_PER_BLOCK;
#pragma unroll
    for (int r = 0; r < ROWS_PER_BLOCK; r++) {
        const int i = i0 + r;
        const float f1 = __ldg(&g_f1[i]);
        const float f2 = __ldg(&g_f2[i]);
        float4 o;
        o.x = fmaf(f1, w1.x, f2 * w2.x);
        o.y = fmaf(f1, w1.y, f2 * w2.y);
        o.z = fmaf(f1, w1.z, f2 * w2.z);
        o.w = fmaf(f1, w1.w, f2 * w2.w);
        out[(size_t)i * NJ4 + j4] = o;
    }
}

// ---------------------------------------------------------------------------
extern "C" void kernel_launch(void* const* d_in, const int* in_sizes, int n_in,
                              void* d_out, int out_size) {
    const float* x    = (const float*)d_in[0];
    const float* a1   = (const float*)d_in[1];
    const float* c1   = (const float*)d_in[2];
    const float* a2   = (const float*)d_in[3];
    const float* c2   = (const float*)d_in[4];
    const float* wfc1 = (const float*)d_in[5];
    const float* bfc1 = (const float*)d_in[6];
    const float* wfc2 = (const float*)d_in[7];
    const float* bfc2 = (const float*)d_in[8];
    float4* out = (float4*)d_out;

    prologue_kernel<<<1, 1024>>>(x, a1, c1, a2, c2, wfc1, bfc1, wfc2, bfc2);
    dim3 grid((NJ4 + 255) / 256, NN / ROWS_PER_BLOCK);
    outer_kernel<<<grid, 256>>>(out);
}

// round 7
// speedup vs baseline: 1.2090x; 1.2090x over previous
#include <cuda_runtime.h>

// Problem constants (fixed by the reference: mulElements hard-codes 8000 rows)
#define NN 8000
#define DD 9
#define NJ4 (NN / 4)            // 2000 float4 per output row
#define ROWS_PER_BLOCK 32

// Scratch (allocation-free rule: __device__ globals). 16B-aligned for float4 IO.
__device__ __align__(16) float g_z1[NN];   // per-row sum ((x-c1)/a1)^2
__device__ __align__(16) float g_z2[NN];
__device__ __align__(16) float g_f1[NN];   // x @ w_fc1.T + b_fc1
__device__ __align__(16) float g_f2[NN];
__device__ __align__(16) float g_w1b[NN];  // normalized cumulative weights
__device__ __align__(16) float g_w2b[NN];

// ---------------------------------------------------------------------------
// Stage 1: per-row quadratic sums + the two 9->1 dot products.
// One thread per row, spread over 125 blocks (~125 SMs) so the 288 KB of x
// reads get chip-wide memory parallelism instead of 32 SMs' worth.
// ---------------------------------------------------------------------------
__global__ __launch_bounds__(64) void rowstats_kernel(
        const float* __restrict__ x,
        const float* __restrict__ a1,
        const float* __restrict__ c1,
        const float* __restrict__ a2,
        const float* __restrict__ c2,
        const float* __restrict__ wfc1,
        const float* __restrict__ bfc1,
        const float* __restrict__ wfc2,
        const float* __restrict__ bfc2) {
    int i = blockIdx.x * 64 + threadIdx.x;
    if (i >= NN) return;
    const float ia1 = 1.0f / a1[0];
    const float ia2 = 1.0f / a2[0];
    const float cc1 = c1[0];
    const float cc2 = c2[0];
    float z1 = 0.0f, z2 = 0.0f;
    float f1 = bfc1[0], f2 = bfc2[0];
#pragma unroll
    for (int j = 0; j < DD; j++) {
        float v = x[i * DD + j];
        float t1 = (v - cc1) * ia1;
        float t2 = (v - cc2) * ia2;
        z1 = fmaf(t1, t1, z1);
        z2 = fmaf(t2, t2, z2);
        f1 = fmaf(v, wfc1[j], f1);
        f2 = fmaf(v, wfc2[j], f2);
    }
    g_z1[i] = z1;
    g_z2[i] = z2;
    g_f1[i] = f1;
    g_f2[i] = f2;
}

// ---------------------------------------------------------------------------
// Stage 2: single-pass block scan. Thread t (t < 1000) owns elements
// [8t, 8t+8): two aligned float4 loads per array, local inclusive cumsum,
// ONE 1024-wide scan of thread totals, then exp/normalize + float4 stores.
// cumprod(prod(exp(-z))) == exp(-cumsum(sum(z))).
// ---------------------------------------------------------------------------
__global__ __launch_bounds__(1024) void scan_kernel() {
    __shared__ float2 s_warp[32];
    const int tid = threadIdx.x;
    const int lane = tid & 31;
    const int wid = tid >> 5;
    const bool live = (tid < NN / 8);   // 1000 live threads

    float la[8], lb[8];
    float ta = 0.0f, tb = 0.0f;
    if (live) {
        const float4* z1v = reinterpret_cast<const float4*>(g_z1);
        const float4* z2v = reinterpret_cast<const float4*>(g_z2);
        float4 a0 = z1v[2 * tid], a1 = z1v[2 * tid + 1];
        float4 b0 = z2v[2 * tid], b1 = z2v[2 * tid + 1];
        la[0] = a0.x; la[1] = a0.y; la[2] = a0.z; la[3] = a0.w;
        la[4] = a1.x; la[5] = a1.y; la[6] = a1.z; la[7] = a1.w;
        lb[0] = b0.x; lb[1] = b0.y; lb[2] = b0.z; lb[3] = b0.w;
        lb[4] = b1.x; lb[5] = b1.y; lb[6] = b1.z; lb[7] = b1.w;
        // local inclusive cumsum
#pragma unroll
        for (int k = 1; k < 8; k++) { la[k] += la[k - 1]; lb[k] += lb[k - 1]; }
        ta = la[7]; tb = lb[7];
    }

    // warp inclusive scan of thread totals
    float sa = ta, sb = tb;
#pragma unroll
    for (int off = 1; off < 32; off <<= 1) {
        float xa = __shfl_up_sync(0xffffffffu, sa, off);
        float xb = __shfl_up_sync(0xffffffffu, sb, off);
        if (lane >= off) { sa += xa; sb += xb; }
    }
    if (lane == 31) s_warp[wid] = make_float2(sa, sb);
    __syncthreads();

    if (wid == 0) {
        float wa = s_warp[lane].x;
        float wb = s_warp[lane].y;
#pragma unroll
        for (int off = 1; off < 32; off <<= 1) {
            float xa = __shfl_up_sync(0xffffffffu, wa, off);
            float xb = __shfl_up_sync(0xffffffffu, wb, off);
            if (lane >= off) { wa += xa; wb += xb; }
        }
        s_warp[lane] = make_float2(wa, wb);
    }
    __syncthreads();

    // exclusive offset for this thread
    float offa = sa - ta;   // exclusive within warp
    float offb = sb - tb;
    if (wid > 0) { offa += s_warp[wid - 1].x; offb += s_warp[wid - 1].y; }

    if (live) {
        float o1[8], o2[8];
#pragma unroll
        for (int k = 0; k < 8; k++) {
            float w1 = expf(-(offa + la[k]));
            float w2 = expf(-(offb + lb[k]));
            float inv = 1.0f / (w1 + w2);
            o1[k] = w1 * inv;
            o2[k] = w2 * inv;
        }
        float4* w1v = reinterpret_cast<float4*>(g_w1b);
        float4* w2v = reinterpret_cast<float4*>(g_w2b);
        w1v[2 * tid]     = make_float4(o1[0], o1[1], o1[2], o1[3]);
        w1v[2 * tid + 1] = make_float4(o1[4], o1[5], o1[6], o1[7]);
        w2v[2 * tid]     = make_float4(o2[0], o2[1], o2[2], o2[3]);
        w2v[2 * tid + 1] = make_float4(o2[4], o2[5], o2[6], o2[7]);
    }
}

// ---------------------------------------------------------------------------
// Stage 3: out[i][j] = f1[i]*w1b[j] + f2[i]*w2b[j]. 256 MB of streaming
// stores — the DRAM-write roofline. __stcs (evict-first) since the output is
// never re-read; 32 rows/block reuse the w float4s in registers.
// ---------------------------------------------------------------------------
__global__ __launch_bounds__(256) void outer_kernel(float4* __restrict__ out) {
    int j4 = blockIdx.x * blockDim.x + threadIdx.x;
    if (j4 >= NJ4) return;

    const float4 w1 = reinterpret_cast<const float4*>(g_w1b)[j4];
    const float4 w2 = reinterpret_cast<const float4*>(g_w2b)[j4];

    const int i0 = blockIdx.y * ROWS_PER_BLOCK;
#pragma unroll
    for (int r = 0; r < ROWS_PER_BLOCK; r++) {
        const int i = i0 + r;
        const float f1 = __ldg(&g_f1[i]);
        const float f2 = __ldg(&g_f2[i]);
        float4 o;
        o.x = fmaf(f1, w1.x, f2 * w2.x);
        o.y = fmaf(f1, w1.y, f2 * w2.y);
        o.z = fmaf(f1, w1.z, f2 * w2.z);
        o.w = fmaf(f1, w1.w, f2 * w2.w);
        __stcs(&out[(size_t)i * NJ4 + j4], o);
    }
}

// ---------------------------------------------------------------------------
extern "C" void kernel_launch(void* const* d_in, const int* in_sizes, int n_in,
                              void* d_out, int out_size) {
    const float* x    = (const float*)d_in[0];
    const float* a1   = (const float*)d_in[1];
    const float* c1   = (const float*)d_in[2];
    const float* a2   = (const float*)d_in[3];
    const float* c2   = (const float*)d_in[4];
    const float* wfc1 = (const float*)d_in[5];
    const float* bfc1 = (const float*)d_in[6];
    const float* wfc2 = (const float*)d_in[7];
    const float* bfc2 = (const float*)d_in[8];
    float4* out = (float4*)d_out;

    rowstats_kernel<<<(NN + 63) / 64, 64>>>(x, a1, c1, a2, c2,
                                            wfc1, bfc1, wfc2, bfc2);
    scan_kernel<<<1, 1024>>>();
    dim3 grid((NJ4 + 255) / 256, NN / ROWS_PER_BLOCK);
    outer_kernel<<<grid, 256>>>(out);
}